// round 4
// baseline (speedup 1.0000x reference)
#include <cuda_runtime.h>
#include <cuda_bf16.h>
#include <math.h>
#include <stdint.h>

#define N_NODES 150000
#define N_ETYPES 1000
#define B_EDGES 16384
#define H 128
#define P_IN 336
#define P_HID 64

// Node GEMM: z[150000, 512] = A_ext[150000, 576] @ W_ext[576, 512]  (bf16-split)
// K passes: kt 0-11 A_hi x W_hi, kt 12-23 A_hi x W_lo, kt 24-35 A_lo x W_hi
// N layout: n = 4*h + g (gates interleaved)
#define KTILES 36
#define KSLICES 24             // packed W slices: 0-11 = W_hi, 12-23 = W_lo
#define MTILE 128
#define M_TILES ((N_NODES + MTILE - 1) / MTILE)   // 1172
#define ASTRIDE 392            // padded K stride (bf16): conflict-free ldmatrix
#define SMEM_BYTES (128 * ASTRIDE * 2)            // 100352

// W fragments, lane-contiguous: [slice(24)][grp(8)][lane(32)][16 u32]
// grp = n8>>3 ; within lane block: u32 index = nt*2 + reg  (nt = n8&7)
__device__ __align__(16) uint32_t g_Wpack[KSLICES * 8 * 32 * 16];
// Transposed W1 for edge MLP: [64][336]
__device__ __align__(16) float g_W1T[P_HID * P_IN];

// ---------------------------------------------------------------------------
__device__ __forceinline__ unsigned short f2bf_bits(float f) {
    return __bfloat16_as_ushort(__float2bfloat16_rn(f));
}
__device__ __forceinline__ float bf_val(unsigned short u) {
    return __bfloat162float(__ushort_as_bfloat16(u));
}
__device__ __forceinline__ float sigmoidf_(float x) { return 1.0f / (1.0f + expf(-x)); }

__device__ __forceinline__ uint32_t smem_u32(const void* p) {
    uint32_t a;
    asm("{ .reg .u64 t; cvta.to.shared.u64 t, %1; cvt.u32.u64 %0, t; }"
        : "=r"(a) : "l"(p));
    return a;
}
__device__ __forceinline__ void ldmatrix_x4(uint32_t* r, uint32_t addr) {
    asm volatile("ldmatrix.sync.aligned.m8n8.x4.shared.b16 {%0,%1,%2,%3}, [%4];"
        : "=r"(r[0]), "=r"(r[1]), "=r"(r[2]), "=r"(r[3]) : "r"(addr));
}
__device__ __forceinline__ void mma16816(float* c, const uint32_t* a, uint32_t bx, uint32_t by) {
    asm volatile("mma.sync.aligned.m16n8k16.row.col.f32.bf16.bf16.f32 "
        "{%0,%1,%2,%3}, {%4,%5,%6,%7}, {%8,%9}, {%0,%1,%2,%3};"
        : "+f"(c[0]), "+f"(c[1]), "+f"(c[2]), "+f"(c[3])
        : "r"(a[0]), "r"(a[1]), "r"(a[2]), "r"(a[3]), "r"(bx), "r"(by));
}

// ---------------------------------------------------------------------------
// W_ext element (bf16 bits) at extended-K index kk, output col n.
// kk in [0,192): hi ; [192,384): lo of same k.
// ---------------------------------------------------------------------------
__device__ __forceinline__ unsigned short wext_bits(
    int kk, int n, const float* Wx, const float* Wh, const float* bg)
{
    int k; bool want_lo = false;
    if (kk < 192) k = kk;
    else          { k = kk - 192; want_lo = true; }
    int g = n & 3, h = n >> 2;
    float w;
    if (k < 128)       w = Wh[(g * 128 + k) * 128 + h];
    else if (k < 178)  w = Wx[(g * 50 + (k - 128)) * 128 + h];
    else if (k == 178) w = bg[g * 128 + h];
    else               w = 0.0f;
    unsigned short hi = f2bf_bits(w);
    if (!want_lo) return hi;
    return f2bf_bits(w - bf_val(hi));
}

__global__ void prep_weights_kernel(const float* __restrict__ Wx,
                                    const float* __restrict__ Wh,
                                    const float* __restrict__ bg,
                                    const float* __restrict__ W1)
{
    int idx = blockIdx.x * blockDim.x + threadIdx.x;
    if (idx < KSLICES * 8 * 32 * 16) {
        // decode lane-contiguous layout
        int reg  = idx & 1;
        int nt   = (idx >> 1) & 7;
        int lane = (idx >> 4) & 31;
        int grp  = (idx >> 9) & 7;
        int sl   = idx >> 12;                 // 0..23
        int n    = (grp * 8 + nt) * 8 + (lane >> 2);
        int kk0  = ((sl < 12) ? sl * 16 : 192 + (sl - 12) * 16)
                   + (lane & 3) * 2 + reg * 8;
        unsigned short u0 = wext_bits(kk0,     n, Wx, Wh, bg);
        unsigned short u1 = wext_bits(kk0 + 1, n, Wx, Wh, bg);
        g_Wpack[idx] = (uint32_t)u0 | ((uint32_t)u1 << 16);
    }
    // transpose W1 (21504 elems)
    int t = blockIdx.x * blockDim.x + threadIdx.x;
    if (t < P_HID * P_IN) {
        int j = t / P_IN, i = t % P_IN;
        g_W1T[t] = W1[i * P_HID + j];
    }
}

// ---------------------------------------------------------------------------
// Node update: bf16-split mma.sync GEMM + fused peephole LSTM.
// 512 threads = 16 warps (4m x 4n), CTA tile 128 nodes x 256 cols (= 64 h).
// ---------------------------------------------------------------------------
__global__ void __launch_bounds__(512, 1) node_update_mma_kernel(
    const float* __restrict__ node_cont,
    const int*   __restrict__ ncat_codes,
    const float* __restrict__ ncat_emb,
    const float* __restrict__ h_prev,
    const float* __restrict__ c_prev,
    const float* __restrict__ w_c,
    float* __restrict__ h_new,
    float* __restrict__ c_new)
{
    extern __shared__ __align__(16) unsigned char smraw[];
    __nv_bfloat16* As  = (__nv_bfloat16*)smraw;   // [128][ASTRIDE]
    float*         zsm = (float*)smraw;           // reused post-GEMM: [64][256]

    const int tid  = threadIdx.x;
    const int lane = tid & 31;
    const int wid  = tid >> 5;
    const int wm   = wid & 3;
    const int wn   = wid >> 2;
    const int mtile = blockIdx.x >> 1;
    const int chunk = blockIdx.x & 1;
    const int n0m   = mtile * MTILE;

    // ---- A build: hi cols [0,192), lo cols [192,384)
    #pragma unroll
    for (int it = 0; it < 4; ++it) {
        int cid = tid + it * 512;
        int row = cid >> 4, kb = (cid & 15) << 3;
        int node = n0m + row;
        float f[8];
        if (node < N_NODES) {
            const float4* hp = (const float4*)(h_prev + (size_t)node * H + kb);
            float4 a = hp[0], b = hp[1];
            f[0]=a.x; f[1]=a.y; f[2]=a.z; f[3]=a.w;
            f[4]=b.x; f[5]=b.y; f[6]=b.z; f[7]=b.w;
        } else {
            #pragma unroll
            for (int q = 0; q < 8; ++q) f[q] = 0.0f;
        }
        uint32_t hw[4], lw[4];
        #pragma unroll
        for (int q = 0; q < 4; ++q) {
            unsigned short h0 = f2bf_bits(f[2*q]),   h1 = f2bf_bits(f[2*q+1]);
            unsigned short l0 = f2bf_bits(f[2*q]   - bf_val(h0));
            unsigned short l1 = f2bf_bits(f[2*q+1] - bf_val(h1));
            hw[q] = (uint32_t)h0 | ((uint32_t)h1 << 16);
            lw[q] = (uint32_t)l0 | ((uint32_t)l1 << 16);
        }
        *(uint4*)&As[row * ASTRIDE + kb]       = make_uint4(hw[0], hw[1], hw[2], hw[3]);
        *(uint4*)&As[row * ASTRIDE + 192 + kb] = make_uint4(lw[0], lw[1], lw[2], lw[3]);
    }
    #pragma unroll 2
    for (int it = 0; it < 16; ++it) {
        int e = tid + it * 512;
        int row = e >> 6, kr = e & 63;
        int node = n0m + row;
        float v = 0.0f;
        if (node < N_NODES) {
            if (kr < 2)        v = node_cont[node * 2 + kr];
            else if (kr < 50)  {
                int j = (kr - 2) >> 4, kd = (kr - 2) & 15;
                int code = ncat_codes[j * N_NODES + node];
                v = ncat_emb[(j * 64 + code) * 16 + kd];
            } else if (kr == 50) v = 1.0f;
        }
        unsigned short hi = f2bf_bits(v);
        As[row * ASTRIDE + 128 + kr] = __ushort_as_bfloat16(hi);
        As[row * ASTRIDE + 320 + kr] = __ushort_as_bfloat16(f2bf_bits(v - bf_val(hi)));
    }
    __syncthreads();

    // ---- GEMM mainloop with B register double-buffer prefetch
    float acc[2][8][4];
    #pragma unroll
    for (int mt = 0; mt < 2; ++mt)
        #pragma unroll
        for (int nt = 0; nt < 8; ++nt)
            #pragma unroll
            for (int q = 0; q < 4; ++q) acc[mt][nt][q] = 0.0f;

    const uint32_t as_base = smem_u32(As);
    const int cg = chunk * 4 + wn;

    uint4 breg[2][4];
    {   // prefetch slice 0
        const uint4* p = (const uint4*)(g_Wpack + ((size_t)(0 * 8 + cg) * 32 + lane) * 16);
        breg[0][0] = p[0]; breg[0][1] = p[1]; breg[0][2] = p[2]; breg[0][3] = p[3];
    }

    #pragma unroll 1
    for (int kt = 0; kt < KTILES; ++kt) {
        const int cur = kt & 1;
        if (kt + 1 < KTILES) {
            int sn = kt + 1;
            int sl = (sn < KSLICES) ? sn : sn - KSLICES;
            const uint4* p = (const uint4*)(g_Wpack + ((size_t)(sl * 8 + cg) * 32 + lane) * 16);
            breg[cur ^ 1][0] = p[0]; breg[cur ^ 1][1] = p[1];
            breg[cur ^ 1][2] = p[2]; breg[cur ^ 1][3] = p[3];
        }
        int acol = (kt < 12) ? kt * 16
                 : (kt < 24) ? (kt - 12) * 16
                 : 192 + (kt - 24) * 16;
        uint32_t a[2][4];
        #pragma unroll
        for (int mt = 0; mt < 2; ++mt) {
            uint32_t addr = as_base +
                ((uint32_t)(wm * 32 + mt * 16 + (lane & 15)) * ASTRIDE
                 + acol + (lane >> 4) * 8) * 2;
            ldmatrix_x4(a[mt], addr);
        }
        #pragma unroll
        for (int q = 0; q < 4; ++q) {
            uint4 bq = breg[cur][q];
            mma16816(acc[0][2*q],   a[0], bq.x, bq.y);
            mma16816(acc[1][2*q],   a[1], bq.x, bq.y);
            mma16816(acc[0][2*q+1], a[0], bq.z, bq.w);
            mma16816(acc[1][2*q+1], a[1], bq.z, bq.w);
        }
    }

    // ---- epilogue: two 64-node halves through smem, fused LSTM
    const int group = lane >> 2;
    const int qq    = lane & 3;
    #pragma unroll
    for (int half = 0; half < 2; ++half) {
        __syncthreads();
        if ((wm >> 1) == half) {
            int rbase = (wm & 1) * 32;
            #pragma unroll
            for (int mt = 0; mt < 2; ++mt) {
                int r = rbase + mt * 16 + group;
                #pragma unroll
                for (int nt = 0; nt < 8; ++nt) {
                    int l = wn * 64 + nt * 8 + qq * 2;
                    *(float2*)&zsm[r * 256 + l] =
                        make_float2(acc[mt][nt][0], acc[mt][nt][1]);
                    *(float2*)&zsm[(r + 8) * 256 + l] =
                        make_float2(acc[mt][nt][2], acc[mt][nt][3]);
                }
            }
        }
        __syncthreads();
        #pragma unroll
        for (int i = 0; i < 8; ++i) {
            int cell = tid + i * 512;
            int nl = cell >> 6, hl = cell & 63;
            int node = n0m + half * 64 + nl;
            if (node < N_NODES) {
                int h = chunk * 64 + hl;
                float4 z = *(const float4*)&zsm[nl * 256 + hl * 4];
                size_t off = (size_t)node * H + h;
                float cv = c_prev[off];
                float ig = sigmoidf_(z.x + w_c[h] * cv);
                float fg = sigmoidf_(z.y + w_c[128 + h] * cv);
                float tg = tanhf(z.z);
                float cn = fg * cv + ig * tg;
                float og = sigmoidf_(z.w + w_c[256 + h] * cn);
                c_new[off] = cn;
                h_new[off] = og * tanhf(cn);
            }
        }
    }
}

// ---------------------------------------------------------------------------
// Edge MLP: 16 edges per block (256 thr = 4 groups x 64 j, 4 edges/thread).
// Each W1 column load feeds 4 FMAs.
// ---------------------------------------------------------------------------
__global__ void __launch_bounds__(256) edge_mlp_kernel(
    const int*   __restrict__ src_ids, const int* __restrict__ dst_ids,
    const int*   __restrict__ etype_ids, const float* __restrict__ t_rel,
    const int*   __restrict__ ecat_codes, const float* __restrict__ eid_emb,
    const float* __restrict__ ecat_emb, const float* __restrict__ time_W,
    const float* __restrict__ time_b,
    const float* __restrict__ W1,
    const float* __restrict__ b1, const float* __restrict__ W2,
    const float* __restrict__ b2, const float* __restrict__ h_new,
    float* __restrict__ prob)
{
    __shared__ float comb[16][P_IN];
    __shared__ float part[4][2][4];

    const int tid  = threadIdx.x;
    const int g    = tid >> 6;        // group 0..3
    const int j    = tid & 63;        // hidden unit
    const int base = blockIdx.x * 16;

    // ---- build 16 comb vectors
    for (int idx = tid; idx < 16 * P_IN; idx += 256) {
        int le  = idx / P_IN;
        int off = idx - le * P_IN;
        int b = base + le;
        float v;
        if (off < 128) {
            v = h_new[(size_t)src_ids[b] * H + off];
        } else if (off < 256) {
            v = h_new[(size_t)dst_ids[b] * H + (off - 128)];
        } else {
            int e = etype_ids[b];
            if (off < 288)       v = eid_emb[e * 32 + (off - 256)];
            else if (off < 304)  { int c0 = ecat_codes[e];
                                   v = ecat_emb[c0 * 16 + (off - 288)]; }
            else if (off < 320)  { int c1 = ecat_codes[N_ETYPES + e];
                                   v = ecat_emb[(32 + c1) * 16 + (off - 304)]; }
            else                 { int k = off - 320;
                                   v = fmaf(t_rel[b], time_W[k], time_b[k]); }
        }
        comb[le][off] = v;
    }
    __syncthreads();

    // ---- hidden layer for 4 edges at once
    float bj = b1[j];
    float h0 = bj, h1 = bj, h2 = bj, h3 = bj;
    const float* c0 = comb[g * 4 + 0];
    const float* c1 = comb[g * 4 + 1];
    const float* c2 = comb[g * 4 + 2];
    const float* c3 = comb[g * 4 + 3];
    #pragma unroll 4
    for (int i = 0; i < P_IN; ++i) {
        float w = W1[i * P_HID + j];
        h0 = fmaf(c0[i], w, h0);
        h1 = fmaf(c1[i], w, h1);
        h2 = fmaf(c2[i], w, h2);
        h3 = fmaf(c3[i], w, h3);
    }
    float w2 = W2[j];
    float v0 = fmaxf(h0, 0.0f) * w2;
    float v1 = fmaxf(h1, 0.0f) * w2;
    float v2 = fmaxf(h2, 0.0f) * w2;
    float v3 = fmaxf(h3, 0.0f) * w2;

    #pragma unroll
    for (int off = 16; off > 0; off >>= 1) {
        v0 += __shfl_down_sync(0xffffffffu, v0, off);
        v1 += __shfl_down_sync(0xffffffffu, v1, off);
        v2 += __shfl_down_sync(0xffffffffu, v2, off);
        v3 += __shfl_down_sync(0xffffffffu, v3, off);
    }
    if ((j & 31) == 0) {
        int wh = j >> 5;
        part[g][wh][0] = v0; part[g][wh][1] = v1;
        part[g][wh][2] = v2; part[g][wh][3] = v3;
    }
    __syncthreads();
    if (j < 4) {
        float zsum = part[g][0][j] + part[g][1][j] + b2[0];
        prob[base + g * 4 + j] = 1.0f / (1.0f + expf(-zsum));
    }
}

// ---------------------------------------------------------------------------
extern "C" void kernel_launch(void* const* d_in, const int* in_sizes, int n_in,
                              void* d_out, int out_size)
{
    const int*   src_ids    = (const int*)  d_in[0];
    const int*   dst_ids    = (const int*)  d_in[1];
    const int*   etype_ids  = (const int*)  d_in[2];
    const float* t_rel      = (const float*)d_in[3];
    const float* node_cont  = (const float*)d_in[4];
    const int*   ncat_codes = (const int*)  d_in[5];
    const int*   ecat_codes = (const int*)  d_in[6];
    /* d_in[7] = edge_index, unused */
    const float* h_prev     = (const float*)d_in[8];
    const float* c_prev     = (const float*)d_in[9];
    const float* ncat_emb   = (const float*)d_in[10];
    const float* eid_emb    = (const float*)d_in[11];
    const float* ecat_emb   = (const float*)d_in[12];
    const float* time_W     = (const float*)d_in[13];
    const float* time_b     = (const float*)d_in[14];
    const float* Wx         = (const float*)d_in[15];
    const float* Wh         = (const float*)d_in[16];
    const float* b_gate     = (const float*)d_in[17];
    const float* w_c        = (const float*)d_in[18];
    const float* W1         = (const float*)d_in[19];
    const float* b1         = (const float*)d_in[20];
    const float* W2         = (const float*)d_in[21];
    const float* b2         = (const float*)d_in[22];

    float* out   = (float*)d_out;
    float* prob  = out;
    float* h_new = out + B_EDGES;
    float* c_new = out + B_EDGES + (size_t)N_NODES * H;

    cudaFuncSetAttribute(node_update_mma_kernel,
                         cudaFuncAttributeMaxDynamicSharedMemorySize, SMEM_BYTES);

    prep_weights_kernel<<<(KSLICES * 8 * 32 * 16 + 255) / 256, 256>>>(Wx, Wh, b_gate, W1);

    node_update_mma_kernel<<<M_TILES * 2, 512, SMEM_BYTES>>>(
        node_cont, ncat_codes, ncat_emb, h_prev, c_prev, w_c, h_new, c_new);

    edge_mlp_kernel<<<B_EDGES / 16, 256>>>(
        src_ids, dst_ids, etype_ids, t_rel,
        ecat_codes, eid_emb, ecat_emb, time_W, time_b,
        W1, b1, W2, b2, h_new, prob);
}

// round 5
// speedup vs baseline: 1.7161x; 1.7161x over previous
#include <cuda_runtime.h>
#include <cuda_bf16.h>
#include <math.h>
#include <stdint.h>

#define N_NODES 150000
#define N_ETYPES 1000
#define B_EDGES 16384
#define H 128
#define P_IN 336
#define P_HID 64

// Node GEMM: z[150000, 512] = A_ext[150000, 576] @ W_ext[576, 512]  (bf16-split)
// K passes: kt 0-11 A_hi x W_hi, kt 12-23 A_hi x W_lo, kt 24-35 A_lo x W_hi
// N layout: n = 4*h + g (gates interleaved)
#define KTILES 36
#define KSLICES 24             // stored W slices: 0-11 = W_hi, 12-23 = W_lo (hi dedup'd)
#define MTILE 128
#define M_TILES ((N_NODES + MTILE - 1) / MTILE)   // 1172
#define ASTRIDE 392            // padded K stride (bf16): conflict-free ldmatrix
#define SMEM_BYTES (128 * ASTRIDE * 2)            // 100352

// W fragments (R3 layout, dedup'd): [slice(24)][n8(64)][lane(32)*2 u32]
__device__ __align__(16) uint32_t g_Wpack[KSLICES * 64 * 64];

// ---------------------------------------------------------------------------
__device__ __forceinline__ unsigned short f2bf_bits(float f) {
    return __bfloat16_as_ushort(__float2bfloat16_rn(f));
}
__device__ __forceinline__ float bf_val(unsigned short u) {
    return __bfloat162float(__ushort_as_bfloat16(u));
}
__device__ __forceinline__ float sigmoidf_(float x) { return 1.0f / (1.0f + expf(-x)); }

__device__ __forceinline__ uint32_t smem_u32(const void* p) {
    uint32_t a;
    asm("{ .reg .u64 t; cvta.to.shared.u64 t, %1; cvt.u32.u64 %0, t; }"
        : "=r"(a) : "l"(p));
    return a;
}
__device__ __forceinline__ void ldmatrix_x4(uint32_t* r, uint32_t addr) {
    asm volatile("ldmatrix.sync.aligned.m8n8.x4.shared.b16 {%0,%1,%2,%3}, [%4];"
        : "=r"(r[0]), "=r"(r[1]), "=r"(r[2]), "=r"(r[3]) : "r"(addr));
}
__device__ __forceinline__ void mma16816(float* c, const uint32_t* a, uint2 b) {
    asm volatile("mma.sync.aligned.m16n8k16.row.col.f32.bf16.bf16.f32 "
        "{%0,%1,%2,%3}, {%4,%5,%6,%7}, {%8,%9}, {%0,%1,%2,%3};"
        : "+f"(c[0]), "+f"(c[1]), "+f"(c[2]), "+f"(c[3])
        : "r"(a[0]), "r"(a[1]), "r"(a[2]), "r"(a[3]), "r"(b.x), "r"(b.y));
}

// ---------------------------------------------------------------------------
// W_ext element (bf16 bits): kk in [0,192) = hi of k, [192,384) = lo of k.
// ---------------------------------------------------------------------------
__device__ __forceinline__ unsigned short wext_bits(
    int kk, int n, const float* Wx, const float* Wh, const float* bg)
{
    int k; bool want_lo = false;
    if (kk < 192) k = kk;
    else          { k = kk - 192; want_lo = true; }
    int g = n & 3, h = n >> 2;
    float w;
    if (k < 128)       w = Wh[(g * 128 + k) * 128 + h];
    else if (k < 178)  w = Wx[(g * 50 + (k - 128)) * 128 + h];
    else if (k == 178) w = bg[g * 128 + h];
    else               w = 0.0f;
    unsigned short hi = f2bf_bits(w);
    if (!want_lo) return hi;
    return f2bf_bits(w - bf_val(hi));
}

__global__ void prep_weights_kernel(const float* __restrict__ Wx,
                                    const float* __restrict__ Wh,
                                    const float* __restrict__ bg)
{
    int idx = blockIdx.x * blockDim.x + threadIdx.x;
    if (idx >= KSLICES * 64 * 64) return;
    int r    = idx & 63;          // lane*2 + reg
    int lane = r >> 1, reg = r & 1;
    int blk  = idx >> 6;          // sl*64 + n8
    int sl   = blk >> 6, n8 = blk & 63;
    int n    = n8 * 8 + (lane >> 2);
    int kk0  = ((sl < 12) ? sl * 16 : 192 + (sl - 12) * 16)
               + (lane & 3) * 2 + reg * 8;
    unsigned short u0 = wext_bits(kk0,     n, Wx, Wh, bg);
    unsigned short u1 = wext_bits(kk0 + 1, n, Wx, Wh, bg);
    g_Wpack[idx] = (uint32_t)u0 | ((uint32_t)u1 << 16);
}

// ---------------------------------------------------------------------------
// Node update: bf16-split mma.sync GEMM + fused peephole LSTM.
// 512 threads = 16 warps (4m x 4n), CTA tile 128 nodes x 256 cols (= 64 h).
// (Exact R3 mainloop structure — verified 569us — with dedup'd W indexing.)
// ---------------------------------------------------------------------------
__global__ void __launch_bounds__(512, 1) node_update_mma_kernel(
    const float* __restrict__ node_cont,
    const int*   __restrict__ ncat_codes,
    const float* __restrict__ ncat_emb,
    const float* __restrict__ h_prev,
    const float* __restrict__ c_prev,
    const float* __restrict__ w_c,
    float* __restrict__ h_new,
    float* __restrict__ c_new)
{
    extern __shared__ __align__(16) unsigned char smraw[];
    __nv_bfloat16* As  = (__nv_bfloat16*)smraw;   // [128][ASTRIDE]
    float*         zsm = (float*)smraw;           // reused post-GEMM: [64][256]

    const int tid  = threadIdx.x;
    const int lane = tid & 31;
    const int wid  = tid >> 5;
    const int wm   = wid & 3;
    const int wn   = wid >> 2;
    const int mtile = blockIdx.x >> 1;
    const int chunk = blockIdx.x & 1;
    const int n0m   = mtile * MTILE;

    // ---- A build: hi cols [0,192), lo cols [192,384)
    #pragma unroll
    for (int it = 0; it < 4; ++it) {
        int cid = tid + it * 512;
        int row = cid >> 4, kb = (cid & 15) << 3;
        int node = n0m + row;
        float f[8];
        if (node < N_NODES) {
            const float4* hp = (const float4*)(h_prev + (size_t)node * H + kb);
            float4 a = hp[0], b = hp[1];
            f[0]=a.x; f[1]=a.y; f[2]=a.z; f[3]=a.w;
            f[4]=b.x; f[5]=b.y; f[6]=b.z; f[7]=b.w;
        } else {
            #pragma unroll
            for (int q = 0; q < 8; ++q) f[q] = 0.0f;
        }
        uint32_t hw[4], lw[4];
        #pragma unroll
        for (int q = 0; q < 4; ++q) {
            unsigned short h0 = f2bf_bits(f[2*q]),   h1 = f2bf_bits(f[2*q+1]);
            unsigned short l0 = f2bf_bits(f[2*q]   - bf_val(h0));
            unsigned short l1 = f2bf_bits(f[2*q+1] - bf_val(h1));
            hw[q] = (uint32_t)h0 | ((uint32_t)h1 << 16);
            lw[q] = (uint32_t)l0 | ((uint32_t)l1 << 16);
        }
        *(uint4*)&As[row * ASTRIDE + kb]       = make_uint4(hw[0], hw[1], hw[2], hw[3]);
        *(uint4*)&As[row * ASTRIDE + 192 + kb] = make_uint4(lw[0], lw[1], lw[2], lw[3]);
    }
    #pragma unroll 2
    for (int it = 0; it < 16; ++it) {
        int e = tid + it * 512;
        int row = e >> 6, kr = e & 63;
        int node = n0m + row;
        float v = 0.0f;
        if (node < N_NODES) {
            if (kr < 2)        v = node_cont[node * 2 + kr];
            else if (kr < 50)  {
                int j = (kr - 2) >> 4, kd = (kr - 2) & 15;
                int code = ncat_codes[j * N_NODES + node];
                v = ncat_emb[(j * 64 + code) * 16 + kd];
            } else if (kr == 50) v = 1.0f;
        }
        unsigned short hi = f2bf_bits(v);
        As[row * ASTRIDE + 128 + kr] = __ushort_as_bfloat16(hi);
        As[row * ASTRIDE + 320 + kr] = __ushort_as_bfloat16(f2bf_bits(v - bf_val(hi)));
    }
    __syncthreads();

    // ---- GEMM mainloop (R3 structure)
    float acc[2][8][4];
    #pragma unroll
    for (int mt = 0; mt < 2; ++mt)
        #pragma unroll
        for (int nt = 0; nt < 8; ++nt)
            #pragma unroll
            for (int q = 0; q < 4; ++q) acc[mt][nt][q] = 0.0f;

    const uint32_t as_base = smem_u32(As);
    const uint32_t* __restrict__ wp_base =
        g_Wpack + (size_t)(chunk * 32 + wn * 8) * 64 + lane * 2;

    #pragma unroll 2
    for (int kt = 0; kt < KTILES; ++kt) {
        int acol = (kt < 12) ? kt * 16
                 : (kt < 24) ? (kt - 12) * 16
                 : 192 + (kt - 24) * 16;
        int sl = (kt < KSLICES) ? kt : kt - KSLICES;   // W_hi dedup
        uint32_t a[2][4];
        #pragma unroll
        for (int mt = 0; mt < 2; ++mt) {
            uint32_t addr = as_base +
                ((uint32_t)(wm * 32 + mt * 16 + (lane & 15)) * ASTRIDE
                 + acol + (lane >> 4) * 8) * 2;
            ldmatrix_x4(a[mt], addr);
        }
        uint2 b[8];
        const uint32_t* wp = wp_base + sl * 4096;   // 64 n8 * 64 u32
        #pragma unroll
        for (int nt = 0; nt < 8; ++nt) b[nt] = *(const uint2*)(wp + nt * 64);
        #pragma unroll
        for (int nt = 0; nt < 8; ++nt) {
            mma16816(acc[0][nt], a[0], b[nt]);
            mma16816(acc[1][nt], a[1], b[nt]);
        }
    }

    // ---- epilogue: two 64-node halves through smem, fused LSTM
    const int group = lane >> 2;
    const int qq    = lane & 3;
    #pragma unroll
    for (int half = 0; half < 2; ++half) {
        __syncthreads();
        if ((wm >> 1) == half) {
            int rbase = (wm & 1) * 32;
            #pragma unroll
            for (int mt = 0; mt < 2; ++mt) {
                int r = rbase + mt * 16 + group;
                #pragma unroll
                for (int nt = 0; nt < 8; ++nt) {
                    int l = wn * 64 + nt * 8 + qq * 2;
                    *(float2*)&zsm[r * 256 + l] =
                        make_float2(acc[mt][nt][0], acc[mt][nt][1]);
                    *(float2*)&zsm[(r + 8) * 256 + l] =
                        make_float2(acc[mt][nt][2], acc[mt][nt][3]);
                }
            }
        }
        __syncthreads();
        #pragma unroll
        for (int i = 0; i < 8; ++i) {
            int cell = tid + i * 512;
            int nl = cell >> 6, hl = cell & 63;
            int node = n0m + half * 64 + nl;
            if (node < N_NODES) {
                int h = chunk * 64 + hl;
                float4 z = *(const float4*)&zsm[nl * 256 + hl * 4];
                size_t off = (size_t)node * H + h;
                float cv = c_prev[off];
                float ig = sigmoidf_(z.x + w_c[h] * cv);
                float fg = sigmoidf_(z.y + w_c[128 + h] * cv);
                float tg = tanhf(z.z);
                float cn = fg * cv + ig * tg;
                float og = sigmoidf_(z.w + w_c[256 + h] * cn);
                c_new[off] = cn;
                h_new[off] = og * tanhf(cn);
            }
        }
    }
}

// ---------------------------------------------------------------------------
// Edge MLP: 16 edges per block (256 thr = 4 groups x 64 j, 4 edges/thread).
// Each W1 column load feeds 4 FMAs.
// ---------------------------------------------------------------------------
__global__ void __launch_bounds__(256) edge_mlp_kernel(
    const int*   __restrict__ src_ids, const int* __restrict__ dst_ids,
    const int*   __restrict__ etype_ids, const float* __restrict__ t_rel,
    const int*   __restrict__ ecat_codes, const float* __restrict__ eid_emb,
    const float* __restrict__ ecat_emb, const float* __restrict__ time_W,
    const float* __restrict__ time_b,
    const float* __restrict__ W1,
    const float* __restrict__ b1, const float* __restrict__ W2,
    const float* __restrict__ b2, const float* __restrict__ h_new,
    float* __restrict__ prob)
{
    __shared__ float comb[16][P_IN];
    __shared__ float part[4][2][4];

    const int tid  = threadIdx.x;
    const int g    = tid >> 6;        // group 0..3
    const int j    = tid & 63;        // hidden unit
    const int base = blockIdx.x * 16;

    // ---- build 16 comb vectors
    for (int idx = tid; idx < 16 * P_IN; idx += 256) {
        int le  = idx / P_IN;
        int off = idx - le * P_IN;
        int b = base + le;
        float v;
        if (off < 128) {
            v = h_new[(size_t)src_ids[b] * H + off];
        } else if (off < 256) {
            v = h_new[(size_t)dst_ids[b] * H + (off - 128)];
        } else {
            int e = etype_ids[b];
            if (off < 288)       v = eid_emb[e * 32 + (off - 256)];
            else if (off < 304)  { int c0 = ecat_codes[e];
                                   v = ecat_emb[c0 * 16 + (off - 288)]; }
            else if (off < 320)  { int c1 = ecat_codes[N_ETYPES + e];
                                   v = ecat_emb[(32 + c1) * 16 + (off - 304)]; }
            else                 { int k = off - 320;
                                   v = fmaf(t_rel[b], time_W[k], time_b[k]); }
        }
        comb[le][off] = v;
    }
    __syncthreads();

    // ---- hidden layer for 4 edges at once
    float bj = b1[j];
    float h0 = bj, h1 = bj, h2 = bj, h3 = bj;
    const float* c0 = comb[g * 4 + 0];
    const float* c1 = comb[g * 4 + 1];
    const float* c2 = comb[g * 4 + 2];
    const float* c3 = comb[g * 4 + 3];
    #pragma unroll 4
    for (int i = 0; i < P_IN; ++i) {
        float w = W1[i * P_HID + j];
        h0 = fmaf(c0[i], w, h0);
        h1 = fmaf(c1[i], w, h1);
        h2 = fmaf(c2[i], w, h2);
        h3 = fmaf(c3[i], w, h3);
    }
    float w2 = W2[j];
    float v0 = fmaxf(h0, 0.0f) * w2;
    float v1 = fmaxf(h1, 0.0f) * w2;
    float v2 = fmaxf(h2, 0.0f) * w2;
    float v3 = fmaxf(h3, 0.0f) * w2;

    #pragma unroll
    for (int off = 16; off > 0; off >>= 1) {
        v0 += __shfl_down_sync(0xffffffffu, v0, off);
        v1 += __shfl_down_sync(0xffffffffu, v1, off);
        v2 += __shfl_down_sync(0xffffffffu, v2, off);
        v3 += __shfl_down_sync(0xffffffffu, v3, off);
    }
    if ((j & 31) == 0) {
        int wh = j >> 5;
        part[g][wh][0] = v0; part[g][wh][1] = v1;
        part[g][wh][2] = v2; part[g][wh][3] = v3;
    }
    __syncthreads();
    if (j < 4) {
        float zsum = part[g][0][j] + part[g][1][j] + b2[0];
        prob[base + g * 4 + j] = 1.0f / (1.0f + expf(-zsum));
    }
}

// ---------------------------------------------------------------------------
extern "C" void kernel_launch(void* const* d_in, const int* in_sizes, int n_in,
                              void* d_out, int out_size)
{
    const int*   src_ids    = (const int*)  d_in[0];
    const int*   dst_ids    = (const int*)  d_in[1];
    const int*   etype_ids  = (const int*)  d_in[2];
    const float* t_rel      = (const float*)d_in[3];
    const float* node_cont  = (const float*)d_in[4];
    const int*   ncat_codes = (const int*)  d_in[5];
    const int*   ecat_codes = (const int*)  d_in[6];
    /* d_in[7] = edge_index, unused */
    const float* h_prev     = (const float*)d_in[8];
    const float* c_prev     = (const float*)d_in[9];
    const float* ncat_emb   = (const float*)d_in[10];
    const float* eid_emb    = (const float*)d_in[11];
    const float* ecat_emb   = (const float*)d_in[12];
    const float* time_W     = (const float*)d_in[13];
    const float* time_b     = (const float*)d_in[14];
    const float* Wx         = (const float*)d_in[15];
    const float* Wh         = (const float*)d_in[16];
    const float* b_gate     = (const float*)d_in[17];
    const float* w_c        = (const float*)d_in[18];
    const float* W1         = (const float*)d_in[19];
    const float* b1         = (const float*)d_in[20];
    const float* W2         = (const float*)d_in[21];
    const float* b2         = (const float*)d_in[22];

    float* out   = (float*)d_out;
    float* prob  = out;
    float* h_new = out + B_EDGES;
    float* c_new = out + B_EDGES + (size_t)N_NODES * H;

    cudaFuncSetAttribute(node_update_mma_kernel,
                         cudaFuncAttributeMaxDynamicSharedMemorySize, SMEM_BYTES);

    prep_weights_kernel<<<(KSLICES * 64 * 64 + 255) / 256, 256>>>(Wx, Wh, b_gate);

    node_update_mma_kernel<<<M_TILES * 2, 512, SMEM_BYTES>>>(
        node_cont, ncat_codes, ncat_emb, h_prev, c_prev, w_c, h_new, c_new);

    edge_mlp_kernel<<<B_EDGES / 16, 256>>>(
        src_ids, dst_ids, etype_ids, t_rel,
        ecat_codes, eid_emb, ecat_emb, time_W, time_b,
        W1, b1, W2, b2, h_new, prob);
}